// round 2
// baseline (speedup 1.0000x reference)
#include <cuda_runtime.h>

#define N_NODES 100000
#define N_USERS 60000
#define N_EDGES 1200000
#define D 64

// Scratch (static device globals — no allocation allowed in kernel_launch)
__device__ int   g_cnt[N_NODES];
__device__ int   g_rowptr[N_NODES + 1];
__device__ int   g_fill[N_NODES];
__device__ float g_dinv[N_NODES];
__device__ int   g_col[N_EDGES];
__device__ __align__(16) float g_coef[N_EDGES];
__device__ __align__(16) float g_h[N_NODES * D];   // X @ W result (per layer)
__device__ __align__(16) float g_t[N_NODES * D];   // layer-1 activated output

__global__ void k_zero() {
    int i = blockIdx.x * blockDim.x + threadIdx.x;
    if (i < N_NODES) g_cnt[i] = 0;
}

// edge_index is int32 (JAX x64-disabled downcasts the int64 request).
__global__ void k_hist(const int* __restrict__ ei) {
    int e = blockIdx.x * blockDim.x + threadIdx.x;
    if (e < N_EDGES) atomicAdd(&g_cnt[ei[N_EDGES + e]], 1);
}

// Single-block exclusive scan over g_cnt -> g_rowptr / g_fill, plus dinv = rsqrt(deg+1).
__global__ void k_scan() {
    __shared__ int wsum[32];
    __shared__ int s_total;
    __shared__ int s_carry;
    int tid = threadIdx.x, lane = tid & 31, w = tid >> 5;
    if (tid == 0) s_carry = 0;
    __syncthreads();
    for (int base = 0; base < N_NODES; base += 1024) {
        int i = base + tid;
        int v = (i < N_NODES) ? g_cnt[i] : 0;
        int inc = v;
#pragma unroll
        for (int o = 1; o < 32; o <<= 1) {
            int t = __shfl_up_sync(0xffffffffu, inc, o);
            if (lane >= o) inc += t;
        }
        if (lane == 31) wsum[w] = inc;
        __syncthreads();
        if (w == 0) {
            int s = wsum[lane];
            int si = s;
#pragma unroll
            for (int o = 1; o < 32; o <<= 1) {
                int t = __shfl_up_sync(0xffffffffu, si, o);
                if (lane >= o) si += t;
            }
            wsum[lane] = si - s;           // exclusive warp offsets
            if (lane == 31) s_total = si;  // chunk total
        }
        __syncthreads();
        if (i < N_NODES) {
            int excl = s_carry + wsum[w] + inc - v;
            g_rowptr[i] = excl;
            g_fill[i]   = excl;
            g_dinv[i]   = rsqrtf((float)v + 1.0f);
        }
        __syncthreads();
        if (tid == 0) s_carry += s_total;
        __syncthreads();
    }
    if (tid == 0) g_rowptr[N_NODES] = s_carry;
}

__global__ void k_bin(const int* __restrict__ ei) {
    int e = blockIdx.x * blockDim.x + threadIdx.x;
    if (e >= N_EDGES) return;
    int s = ei[e];
    int d = ei[N_EDGES + e];
    int pos = atomicAdd(&g_fill[d], 1);
    g_col[pos]  = s;
    g_coef[pos] = g_dinv[s] * g_dinv[d];
}

// H = X @ W  (100000x64 @ 64x64). 256 threads/block, 64 rows/block.
// Thread (lr, cg): row lr, cols [cg*16, cg*16+16). W in shared with 17/68 padding
// so the 4 col-groups of a warp hit 4 distinct banks (broadcast x8, conflict-free).
template <int SRC>  // 0: X = input x, 1: X = g_t
__global__ void k_gemm(const float* __restrict__ Xin, const float* __restrict__ W) {
    __shared__ float sW[64 * 68];
    int tid = threadIdx.x;
    for (int i = tid; i < 4096; i += 256) {
        int k = i >> 6, c = i & 63;
        sW[k * 68 + (c >> 4) * 17 + (c & 15)] = W[i];
    }
    __syncthreads();
    const float* X = (SRC == 0) ? Xin : (const float*)g_t;
    int lr = tid >> 2, cg = tid & 3;
    int row = blockIdx.x * 64 + lr;
    if (row >= N_NODES) return;
    const float4* xr = reinterpret_cast<const float4*>(X + (size_t)row * D);
    float acc[16];
#pragma unroll
    for (int j = 0; j < 16; j++) acc[j] = 0.f;
#pragma unroll
    for (int k4 = 0; k4 < 16; k4++) {
        float4 xv = xr[k4];
        const float* wb = &sW[(k4 * 4) * 68 + cg * 17];
#pragma unroll
        for (int kk = 0; kk < 4; kk++) {
            float xs = (kk == 0) ? xv.x : (kk == 1) ? xv.y : (kk == 2) ? xv.z : xv.w;
            const float* wr = wb + kk * 68;
#pragma unroll
            for (int j = 0; j < 16; j++) acc[j] += xs * wr[j];
        }
    }
    float4* o = reinterpret_cast<float4*>(g_h + (size_t)row * D + cg * 16);
    o[0] = make_float4(acc[0], acc[1], acc[2], acc[3]);
    o[1] = make_float4(acc[4], acc[5], acc[6], acc[7]);
    o[2] = make_float4(acc[8], acc[9], acc[10], acc[11]);
    o[3] = make_float4(acc[12], acc[13], acc[14], acc[15]);
}

// SpMM: one warp per dst row, 2 floats/lane, register accumulation, no atomics.
// MODE 1: relu -> g_t. MODE 2: final -> out[row] and out[N_NODES + row] (dup copy).
template <int MODE>
__global__ void k_spmm(const float* __restrict__ bias, float* __restrict__ out) {
    int gwarp = (blockIdx.x * blockDim.x + threadIdx.x) >> 5;
    int lane  = threadIdx.x & 31;
    if (gwarp >= N_NODES) return;
    int row = gwarp;
    float di = g_dinv[row];
    float sc = di * di;
    float2 hv = reinterpret_cast<const float2*>(g_h + (size_t)row * D)[lane];
    float ax = hv.x * sc, ay = hv.y * sc;
    int e = g_rowptr[row], end = g_rowptr[row + 1];
    for (; e < end; e++) {
        int   c  = g_col[e];
        float cf = g_coef[e];
        float2 v = reinterpret_cast<const float2*>(g_h + (size_t)c * D)[lane];
        ax += v.x * cf;
        ay += v.y * cf;
    }
    float2 bv = reinterpret_cast<const float2*>(bias)[lane];
    ax += bv.x;
    ay += bv.y;
    if (MODE == 1) {
        ax = fmaxf(ax, 0.f);
        ay = fmaxf(ay, 0.f);
        reinterpret_cast<float2*>(g_t + (size_t)row * D)[lane] = make_float2(ax, ay);
    } else {
        float2 r = make_float2(ax, ay);
        reinterpret_cast<float2*>(out + (size_t)row * D)[lane] = r;
        reinterpret_cast<float2*>(out + (size_t)(N_NODES + row) * D)[lane] = r;
    }
}

extern "C" void kernel_launch(void* const* d_in, const int* in_sizes, int n_in,
                              void* d_out, int out_size) {
    const float* x  = (const float*)d_in[0];
    const int*   ei = (const int*)d_in[1];
    const float* W1 = (const float*)d_in[2];
    const float* b1 = (const float*)d_in[3];
    const float* W2 = (const float*)d_in[4];
    const float* b2 = (const float*)d_in[5];
    float* out = (float*)d_out;

    k_zero<<<(N_NODES + 255) / 256, 256>>>();
    k_hist<<<(N_EDGES + 255) / 256, 256>>>(ei);
    k_scan<<<1, 1024>>>();
    k_bin<<<(N_EDGES + 255) / 256, 256>>>(ei);

    k_gemm<0><<<(N_NODES + 63) / 64, 256>>>(x, W1);            // g_h = x @ W1
    k_spmm<1><<<(N_NODES * 32 + 255) / 256, 256>>>(b1, out);   // g_t = relu(gcn1)
    k_gemm<1><<<(N_NODES + 63) / 64, 256>>>(x, W2);            // g_h = g_t @ W2
    k_spmm<2><<<(N_NODES * 32 + 255) / 256, 256>>>(b2, out);   // out = [h; h]
}

// round 3
// speedup vs baseline: 1.3618x; 1.3618x over previous
#include <cuda_runtime.h>

#define N_NODES 100000
#define N_USERS 60000
#define N_EDGES 1200000
#define D 64
#define NB 98   // ceil(100000/1024) scan blocks

// Scratch (static device globals — no allocation allowed in kernel_launch)
__device__ int   g_cnt[N_NODES];
__device__ int   g_rowptr[N_NODES + 1];
__device__ int   g_fill[N_NODES];
__device__ float g_dinv[N_NODES];
__device__ int   g_bsum[NB];
__device__ int   g_boff[NB];
__device__ __align__(16) int2  g_edge[N_EDGES];        // (col, coef-bits)
__device__ __align__(16) float g_h[N_NODES * D];       // X @ W result (per layer)
__device__ __align__(16) float g_t[N_NODES * D];       // layer-1 activated output

__global__ void k_zero() {
    int i = blockIdx.x * blockDim.x + threadIdx.x;
    if (i < N_NODES / 4) reinterpret_cast<int4*>(g_cnt)[i] = make_int4(0, 0, 0, 0);
}

// edge_index is int32 (JAX x64-disabled downcasts the int64 request).
__global__ void k_hist(const int* __restrict__ ei) {
    int e = blockIdx.x * blockDim.x + threadIdx.x;
    if (e < N_EDGES) atomicAdd(&g_cnt[ei[N_EDGES + e]], 1);
}

// Pass A: per-1024-chunk reduction + dinv.
__global__ void k_reduce() {
    __shared__ int wsum[32];
    int tid = threadIdx.x, lane = tid & 31, w = tid >> 5;
    int i = blockIdx.x * 1024 + tid;
    int v = (i < N_NODES) ? g_cnt[i] : 0;
    if (i < N_NODES) g_dinv[i] = rsqrtf((float)v + 1.0f);
    int s = v;
#pragma unroll
    for (int o = 16; o > 0; o >>= 1) s += __shfl_down_sync(0xffffffffu, s, o);
    if (lane == 0) wsum[w] = s;
    __syncthreads();
    if (w == 0) {
        int t = wsum[lane];
#pragma unroll
        for (int o = 16; o > 0; o >>= 1) t += __shfl_down_sync(0xffffffffu, t, o);
        if (lane == 0) g_bsum[blockIdx.x] = t;
    }
}

// Pass B: exclusive scan of the NB block sums (single tiny block).
__global__ void k_scanb() {
    __shared__ int ws[4];
    int tid = threadIdx.x, lane = tid & 31, w = tid >> 5;
    int v = (tid < NB) ? g_bsum[tid] : 0;
    int inc = v;
#pragma unroll
    for (int o = 1; o < 32; o <<= 1) {
        int t = __shfl_up_sync(0xffffffffu, inc, o);
        if (lane >= o) inc += t;
    }
    if (lane == 31) ws[w] = inc;
    __syncthreads();
    int off = 0;
    for (int k = 0; k < w; k++) off += ws[k];
    int excl = off + inc - v;
    if (tid < NB) g_boff[tid] = excl;
    if (tid == NB - 1) g_rowptr[N_NODES] = excl + v;
}

// Pass C: per-chunk local exclusive scan + global offset -> rowptr/fill.
__global__ void k_scanc() {
    __shared__ int wsum[32];
    int tid = threadIdx.x, lane = tid & 31, w = tid >> 5;
    int i = blockIdx.x * 1024 + tid;
    int v = (i < N_NODES) ? g_cnt[i] : 0;
    int inc = v;
#pragma unroll
    for (int o = 1; o < 32; o <<= 1) {
        int t = __shfl_up_sync(0xffffffffu, inc, o);
        if (lane >= o) inc += t;
    }
    if (lane == 31) wsum[w] = inc;
    __syncthreads();
    if (w == 0) {
        int s = wsum[lane];
        int si = s;
#pragma unroll
        for (int o = 1; o < 32; o <<= 1) {
            int t = __shfl_up_sync(0xffffffffu, si, o);
            if (lane >= o) si += t;
        }
        wsum[lane] = si - s;
    }
    __syncthreads();
    if (i < N_NODES) {
        int excl = g_boff[blockIdx.x] + wsum[w] + inc - v;
        g_rowptr[i] = excl;
        g_fill[i]   = excl;
    }
}

__global__ void k_bin(const int* __restrict__ ei) {
    int e = blockIdx.x * blockDim.x + threadIdx.x;
    if (e >= N_EDGES) return;
    int s = ei[e];
    int d = ei[N_EDGES + e];
    float cf = g_dinv[s] * g_dinv[d];
    int pos = atomicAdd(&g_fill[d], 1);
    g_edge[pos] = make_int2(s, __float_as_int(cf));
}

// H = X @ W  (100000x64 @ 64x64). 256 threads/block, 64 rows/block.
template <int SRC>  // 0: X = input x, 1: X = g_t
__global__ void k_gemm(const float* __restrict__ Xin, const float* __restrict__ W) {
    __shared__ float sW[64 * 68];
    int tid = threadIdx.x;
    for (int i = tid; i < 4096; i += 256) {
        int k = i >> 6, c = i & 63;
        sW[k * 68 + (c >> 4) * 17 + (c & 15)] = W[i];
    }
    __syncthreads();
    const float* X = (SRC == 0) ? Xin : (const float*)g_t;
    int lr = tid >> 2, cg = tid & 3;
    int row = blockIdx.x * 64 + lr;
    if (row >= N_NODES) return;
    const float4* xr = reinterpret_cast<const float4*>(X + (size_t)row * D);
    float acc[16];
#pragma unroll
    for (int j = 0; j < 16; j++) acc[j] = 0.f;
#pragma unroll
    for (int k4 = 0; k4 < 16; k4++) {
        float4 xv = xr[k4];
        const float* wb = &sW[(k4 * 4) * 68 + cg * 17];
#pragma unroll
        for (int kk = 0; kk < 4; kk++) {
            float xs = (kk == 0) ? xv.x : (kk == 1) ? xv.y : (kk == 2) ? xv.z : xv.w;
            const float* wr = wb + kk * 68;
#pragma unroll
            for (int j = 0; j < 16; j++) acc[j] += xs * wr[j];
        }
    }
    float4* o = reinterpret_cast<float4*>(g_h + (size_t)row * D + cg * 16);
    o[0] = make_float4(acc[0], acc[1], acc[2], acc[3]);
    o[1] = make_float4(acc[4], acc[5], acc[6], acc[7]);
    o[2] = make_float4(acc[8], acc[9], acc[10], acc[11]);
    o[3] = make_float4(acc[12], acc[13], acc[14], acc[15]);
}

// SpMM: 16 lanes per dst row, float4 per lane, register accumulation, no atomics.
// MODE 1: relu -> g_t. MODE 2: final -> out[row] and out[N_NODES + row] (dup copy).
template <int MODE>
__global__ void k_spmm(const float* __restrict__ bias, float* __restrict__ out) {
    int gid = blockIdx.x * blockDim.x + threadIdx.x;
    int row = gid >> 4;
    int l   = gid & 15;
    if (row >= N_NODES) return;
    float di = g_dinv[row];
    float sc = di * di;
    float4 hv = *reinterpret_cast<const float4*>(g_h + (size_t)row * D + l * 4);
    float ax = hv.x * sc, ay = hv.y * sc, az = hv.z * sc, aw = hv.w * sc;
    int e = g_rowptr[row], end = g_rowptr[row + 1];
#pragma unroll 4
    for (; e < end; e++) {
        int2  p  = g_edge[e];
        float cf = __int_as_float(p.y);
        float4 v = *reinterpret_cast<const float4*>(g_h + (size_t)p.x * D + l * 4);
        ax += v.x * cf;
        ay += v.y * cf;
        az += v.z * cf;
        aw += v.w * cf;
    }
    float4 bv = reinterpret_cast<const float4*>(bias)[l];
    ax += bv.x; ay += bv.y; az += bv.z; aw += bv.w;
    if (MODE == 1) {
        float4 r = make_float4(fmaxf(ax, 0.f), fmaxf(ay, 0.f), fmaxf(az, 0.f), fmaxf(aw, 0.f));
        *reinterpret_cast<float4*>(g_t + (size_t)row * D + l * 4) = r;
    } else {
        float4 r = make_float4(ax, ay, az, aw);
        *reinterpret_cast<float4*>(out + (size_t)row * D + l * 4) = r;
        *reinterpret_cast<float4*>(out + (size_t)(N_NODES + row) * D + l * 4) = r;
    }
}

extern "C" void kernel_launch(void* const* d_in, const int* in_sizes, int n_in,
                              void* d_out, int out_size) {
    const float* x  = (const float*)d_in[0];
    const int*   ei = (const int*)d_in[1];
    const float* W1 = (const float*)d_in[2];
    const float* b1 = (const float*)d_in[3];
    const float* W2 = (const float*)d_in[4];
    const float* b2 = (const float*)d_in[5];
    float* out = (float*)d_out;

    k_zero<<<(N_NODES / 4 + 255) / 256, 256>>>();
    k_hist<<<(N_EDGES + 255) / 256, 256>>>(ei);
    k_reduce<<<NB, 1024>>>();
    k_scanb<<<1, 128>>>();
    k_scanc<<<NB, 1024>>>();
    k_bin<<<(N_EDGES + 255) / 256, 256>>>(ei);

    k_gemm<0><<<(N_NODES + 63) / 64, 256>>>(x, W1);             // g_h = x @ W1
    k_spmm<1><<<(N_NODES * 16 + 255) / 256, 256>>>(b1, out);    // g_t = relu(gcn1)
    k_gemm<1><<<(N_NODES + 63) / 64, 256>>>(x, W2);             // g_h = g_t @ W2
    k_spmm<2><<<(N_NODES * 16 + 255) / 256, 256>>>(b2, out);    // out = [h; h]
}

// round 4
// speedup vs baseline: 1.8223x; 1.3382x over previous
#include <cuda_runtime.h>
#include <cstdint>

#define N_NODES 100000
#define N_USERS 60000
#define N_EDGES 1200000
#define D 64
#define NB 98   // ceil(100000/1024) scan blocks

// Scratch (static device globals — no allocation allowed in kernel_launch)
__device__ int   g_cnt[N_NODES];
__device__ int   g_rowptr[N_NODES + 1];
__device__ int   g_fill[N_NODES];
__device__ float g_dinv[N_NODES];
__device__ int   g_bsum[NB];
__device__ int   g_boff[NB];
__device__ __align__(16) int2  g_edge[N_EDGES];        // (col, coef-bits)
__device__ __align__(16) float g_h[N_NODES * D];       // X @ W result (per layer)
__device__ __align__(16) float g_t[N_NODES * D];       // layer-1 activated output

__global__ void k_zero() {
    int i = blockIdx.x * blockDim.x + threadIdx.x;
    if (i < N_NODES / 4) reinterpret_cast<int4*>(g_cnt)[i] = make_int4(0, 0, 0, 0);
}

// edge_index is int32 (JAX x64-disabled downcasts the int64 request).
__global__ void k_hist(const int* __restrict__ ei) {
    int e = blockIdx.x * blockDim.x + threadIdx.x;
    if (e < N_EDGES) atomicAdd(&g_cnt[ei[N_EDGES + e]], 1);
}

// Pass A: per-1024-chunk reduction + dinv.
__global__ void k_reduce() {
    __shared__ int wsum[32];
    int tid = threadIdx.x, lane = tid & 31, w = tid >> 5;
    int i = blockIdx.x * 1024 + tid;
    int v = (i < N_NODES) ? g_cnt[i] : 0;
    if (i < N_NODES) g_dinv[i] = rsqrtf((float)v + 1.0f);
    int s = v;
#pragma unroll
    for (int o = 16; o > 0; o >>= 1) s += __shfl_down_sync(0xffffffffu, s, o);
    if (lane == 0) wsum[w] = s;
    __syncthreads();
    if (w == 0) {
        int t = wsum[lane];
#pragma unroll
        for (int o = 16; o > 0; o >>= 1) t += __shfl_down_sync(0xffffffffu, t, o);
        if (lane == 0) g_bsum[blockIdx.x] = t;
    }
}

// Pass B: exclusive scan of the NB block sums (single tiny block).
__global__ void k_scanb() {
    __shared__ int ws[4];
    int tid = threadIdx.x, lane = tid & 31, w = tid >> 5;
    int v = (tid < NB) ? g_bsum[tid] : 0;
    int inc = v;
#pragma unroll
    for (int o = 1; o < 32; o <<= 1) {
        int t = __shfl_up_sync(0xffffffffu, inc, o);
        if (lane >= o) inc += t;
    }
    if (lane == 31) ws[w] = inc;
    __syncthreads();
    int off = 0;
    for (int k = 0; k < w; k++) off += ws[k];
    int excl = off + inc - v;
    if (tid < NB) g_boff[tid] = excl;
    if (tid == NB - 1) g_rowptr[N_NODES] = excl + v;
}

// Pass C: per-chunk local exclusive scan + global offset -> rowptr/fill.
__global__ void k_scanc() {
    __shared__ int wsum[32];
    int tid = threadIdx.x, lane = tid & 31, w = tid >> 5;
    int i = blockIdx.x * 1024 + tid;
    int v = (i < N_NODES) ? g_cnt[i] : 0;
    int inc = v;
#pragma unroll
    for (int o = 1; o < 32; o <<= 1) {
        int t = __shfl_up_sync(0xffffffffu, inc, o);
        if (lane >= o) inc += t;
    }
    if (lane == 31) wsum[w] = inc;
    __syncthreads();
    if (w == 0) {
        int s = wsum[lane];
        int si = s;
#pragma unroll
        for (int o = 1; o < 32; o <<= 1) {
            int t = __shfl_up_sync(0xffffffffu, si, o);
            if (lane >= o) si += t;
        }
        wsum[lane] = si - s;
    }
    __syncthreads();
    if (i < N_NODES) {
        int excl = g_boff[blockIdx.x] + wsum[w] + inc - v;
        g_rowptr[i] = excl;
        g_fill[i]   = excl;
    }
}

__global__ void k_bin(const int* __restrict__ ei) {
    int e = blockIdx.x * blockDim.x + threadIdx.x;
    if (e >= N_EDGES) return;
    int s = ei[e];
    int d = ei[N_EDGES + e];
    float cf = g_dinv[s] * g_dinv[d];
    int pos = atomicAdd(&g_fill[d], 1);
    g_edge[pos] = make_int2(s, __float_as_int(cf));
}

// ---------------- tf32 MMA GEMM (3xtf32 split for fp32 accuracy) ----------------
__device__ __forceinline__ uint32_t f2tf(float v) {
    uint32_t r;
    asm("cvt.rna.tf32.f32 %0, %1;" : "=r"(r) : "f"(v));
    return r;
}
__device__ __forceinline__ void split_tf(float v, uint32_t& hi, uint32_t& lo) {
    hi = f2tf(v);
    lo = f2tf(v - __uint_as_float(hi));
}
__device__ __forceinline__ void mma8(float4& d, const uint32_t* a, uint32_t b0, uint32_t b1) {
    asm volatile(
        "mma.sync.aligned.m16n8k8.row.col.f32.tf32.tf32.f32 "
        "{%0,%1,%2,%3}, {%4,%5,%6,%7}, {%8,%9}, {%0,%1,%2,%3};"
        : "+f"(d.x), "+f"(d.y), "+f"(d.z), "+f"(d.w)
        : "r"(a[0]), "r"(a[1]), "r"(a[2]), "r"(a[3]), "r"(b0), "r"(b1));
}

// H = X @ W (100000x64 @ 64x64). 128 threads = 4 warps; 16 rows/warp = 64 rows/block.
template <int SRC>  // 0: X = input x, 1: X = g_t
__global__ void __launch_bounds__(128) k_gemm(const float* __restrict__ Xin,
                                              const float* __restrict__ W) {
    __shared__ __align__(16) float sX[64 * 68];  // stride 68: A-frag loads conflict-free
    __shared__ __align__(16) float sW[64 * 72];  // stride 72: B-frag loads conflict-free
    const float* X = (SRC == 0) ? Xin : (const float*)g_t;
    int tid = threadIdx.x, warp = tid >> 5, lane = tid & 31;
    int g = lane >> 2, tq = lane & 3;   // group (0..7), thread-in-quad (0..3)
    int rowbase = blockIdx.x * 64;

    // Load W (64x64) into sW, float4 coalesced.
    for (int i = tid; i < 1024; i += 128) {
        int k = i >> 4, c4 = (i & 15) << 2;
        float4 w = reinterpret_cast<const float4*>(W)[i];
        *reinterpret_cast<float4*>(&sW[k * 72 + c4]) = w;
    }
    // Load X block (64 rows x 64 cols) into sX, zero-padded tail.
    for (int i = tid; i < 1024; i += 128) {
        int r = i >> 4, c4i = i & 15;
        int gr = rowbase + r;
        float4 v = (gr < N_NODES)
                       ? reinterpret_cast<const float4*>(X + (size_t)gr * D)[c4i]
                       : make_float4(0.f, 0.f, 0.f, 0.f);
        *reinterpret_cast<float4*>(&sX[r * 68 + (c4i << 2)]) = v;
    }
    __syncthreads();

    int wr = warp * 16;  // this warp's local row base
    float4 acc[8];
#pragma unroll
    for (int nt = 0; nt < 8; nt++) acc[nt] = make_float4(0.f, 0.f, 0.f, 0.f);

#pragma unroll
    for (int kt = 0; kt < 8; kt++) {
        // A fragments (hi/lo split)
        uint32_t ah[4], al[4];
        {
            float a0 = sX[(wr + g) * 68 + kt * 8 + tq];
            float a1 = sX[(wr + g + 8) * 68 + kt * 8 + tq];
            float a2 = sX[(wr + g) * 68 + kt * 8 + tq + 4];
            float a3 = sX[(wr + g + 8) * 68 + kt * 8 + tq + 4];
            split_tf(a0, ah[0], al[0]);
            split_tf(a1, ah[1], al[1]);
            split_tf(a2, ah[2], al[2]);
            split_tf(a3, ah[3], al[3]);
        }
#pragma unroll
        for (int nt = 0; nt < 8; nt++) {
            float b0f = sW[(kt * 8 + tq) * 72 + nt * 8 + g];
            float b1f = sW[(kt * 8 + tq + 4) * 72 + nt * 8 + g];
            uint32_t bh0, bl0, bh1, bl1;
            split_tf(b0f, bh0, bl0);
            split_tf(b1f, bh1, bl1);
            mma8(acc[nt], ah, bh0, bh1);  // hi*hi
            mma8(acc[nt], al, bh0, bh1);  // lo*hi
            mma8(acc[nt], ah, bl0, bl1);  // hi*lo
        }
    }

    // Store D: rows (rowbase+wr+g) and (+8); cols nt*8 + 2*tq (+1).
    int r0 = rowbase + wr + g;
    int r1 = r0 + 8;
#pragma unroll
    for (int nt = 0; nt < 8; nt++) {
        int c = nt * 8 + tq * 2;
        if (r0 < N_NODES)
            *reinterpret_cast<float2*>(g_h + (size_t)r0 * D + c) = make_float2(acc[nt].x, acc[nt].y);
        if (r1 < N_NODES)
            *reinterpret_cast<float2*>(g_h + (size_t)r1 * D + c) = make_float2(acc[nt].z, acc[nt].w);
    }
}

// ---------------- SpMM: one warp per dst row, float2/lane, 4-wide gather batches ----------------
// MODE 1: relu -> g_t. MODE 2: final -> out[row] and out[N_NODES + row] (dup copy).
template <int MODE>
__global__ void k_spmm(const float* __restrict__ bias, float* __restrict__ out) {
    int warp = (blockIdx.x * blockDim.x + threadIdx.x) >> 5;
    int lane = threadIdx.x & 31;
    if (warp >= N_NODES) return;
    int row = warp;
    float di = g_dinv[row];
    float sc = di * di;
    float2 hv = reinterpret_cast<const float2*>(g_h + (size_t)row * D)[lane];
    float ax = hv.x * sc, ay = hv.y * sc;
    int e = g_rowptr[row], end = g_rowptr[row + 1];
    for (; e + 4 <= end; e += 4) {
        int2 p0 = g_edge[e];
        int2 p1 = g_edge[e + 1];
        int2 p2 = g_edge[e + 2];
        int2 p3 = g_edge[e + 3];
        float2 v0 = reinterpret_cast<const float2*>(g_h + (size_t)p0.x * D)[lane];
        float2 v1 = reinterpret_cast<const float2*>(g_h + (size_t)p1.x * D)[lane];
        float2 v2 = reinterpret_cast<const float2*>(g_h + (size_t)p2.x * D)[lane];
        float2 v3 = reinterpret_cast<const float2*>(g_h + (size_t)p3.x * D)[lane];
        float c0 = __int_as_float(p0.y), c1 = __int_as_float(p1.y);
        float c2 = __int_as_float(p2.y), c3 = __int_as_float(p3.y);
        ax += v0.x * c0; ay += v0.y * c0;
        ax += v1.x * c1; ay += v1.y * c1;
        ax += v2.x * c2; ay += v2.y * c2;
        ax += v3.x * c3; ay += v3.y * c3;
    }
    for (; e < end; e++) {
        int2 p = g_edge[e];
        float cf = __int_as_float(p.y);
        float2 v = reinterpret_cast<const float2*>(g_h + (size_t)p.x * D)[lane];
        ax += v.x * cf;
        ay += v.y * cf;
    }
    float2 bv = reinterpret_cast<const float2*>(bias)[lane];
    ax += bv.x;
    ay += bv.y;
    if (MODE == 1) {
        float2 r = make_float2(fmaxf(ax, 0.f), fmaxf(ay, 0.f));
        reinterpret_cast<float2*>(g_t + (size_t)row * D)[lane] = r;
    } else {
        float2 r = make_float2(ax, ay);
        reinterpret_cast<float2*>(out + (size_t)row * D)[lane] = r;
        reinterpret_cast<float2*>(out + (size_t)(N_NODES + row) * D)[lane] = r;
    }
}

extern "C" void kernel_launch(void* const* d_in, const int* in_sizes, int n_in,
                              void* d_out, int out_size) {
    const float* x  = (const float*)d_in[0];
    const int*   ei = (const int*)d_in[1];
    const float* W1 = (const float*)d_in[2];
    const float* b1 = (const float*)d_in[3];
    const float* W2 = (const float*)d_in[4];
    const float* b2 = (const float*)d_in[5];
    float* out = (float*)d_out;

    k_zero<<<(N_NODES / 4 + 255) / 256, 256>>>();
    k_hist<<<(N_EDGES + 255) / 256, 256>>>(ei);
    k_reduce<<<NB, 1024>>>();
    k_scanb<<<1, 128>>>();
    k_scanc<<<NB, 1024>>>();
    k_bin<<<(N_EDGES + 255) / 256, 256>>>(ei);

    k_gemm<0><<<(N_NODES + 63) / 64, 128>>>(x, W1);             // g_h = x @ W1
    k_spmm<1><<<(N_NODES * 32 + 255) / 256, 256>>>(b1, out);    // g_t = relu(gcn1)
    k_gemm<1><<<(N_NODES + 63) / 64, 128>>>(x, W2);             // g_h = g_t @ W2
    k_spmm<2><<<(N_NODES * 32 + 255) / 256, 256>>>(b2, out);    // out = [h; h]
}

// round 5
// speedup vs baseline: 1.9188x; 1.0529x over previous
#include <cuda_runtime.h>
#include <cuda_fp16.h>
#include <cstdint>

#define N_NODES 100000
#define N_USERS 60000
#define N_EDGES 1200000
#define D 64
#define NB 98   // ceil(100000/1024) scan blocks

// Scratch (static device globals — no allocation allowed in kernel_launch)
__device__ int   g_cnt[N_NODES];
__device__ int   g_rowptr[N_NODES + 1];
__device__ int   g_fill[N_NODES];
__device__ float g_dinv[N_NODES];
__device__ int   g_bsum[NB];
__device__ int   g_boff[NB];
__device__ __align__(16) int2     g_edge[N_EDGES];     // (col, coef-bits)
__device__ __align__(16) float    g_h[N_NODES * D];    // X @ W result, fp32 (self term)
__device__ __align__(16) uint32_t g_hh[N_NODES * 32];  // X @ W result, half2 (gather copy)
__device__ __align__(16) float    g_t[N_NODES * D];    // layer-1 activated output

__global__ void k_zero() {
    int i = blockIdx.x * blockDim.x + threadIdx.x;
    if (i < N_NODES / 4) reinterpret_cast<int4*>(g_cnt)[i] = make_int4(0, 0, 0, 0);
}

// edge_index is int32 (JAX x64-disabled downcasts the int64 request).
__global__ void k_hist(const int* __restrict__ ei) {
    int e = blockIdx.x * blockDim.x + threadIdx.x;
    if (e < N_EDGES) atomicAdd(&g_cnt[ei[N_EDGES + e]], 1);
}

// Pass A: per-1024-chunk reduction + dinv.
__global__ void k_reduce() {
    __shared__ int wsum[32];
    int tid = threadIdx.x, lane = tid & 31, w = tid >> 5;
    int i = blockIdx.x * 1024 + tid;
    int v = (i < N_NODES) ? g_cnt[i] : 0;
    if (i < N_NODES) g_dinv[i] = rsqrtf((float)v + 1.0f);
    int s = v;
#pragma unroll
    for (int o = 16; o > 0; o >>= 1) s += __shfl_down_sync(0xffffffffu, s, o);
    if (lane == 0) wsum[w] = s;
    __syncthreads();
    if (w == 0) {
        int t = wsum[lane];
#pragma unroll
        for (int o = 16; o > 0; o >>= 1) t += __shfl_down_sync(0xffffffffu, t, o);
        if (lane == 0) g_bsum[blockIdx.x] = t;
    }
}

// Pass B: exclusive scan of the NB block sums (single tiny block).
__global__ void k_scanb() {
    __shared__ int ws[4];
    int tid = threadIdx.x, lane = tid & 31, w = tid >> 5;
    int v = (tid < NB) ? g_bsum[tid] : 0;
    int inc = v;
#pragma unroll
    for (int o = 1; o < 32; o <<= 1) {
        int t = __shfl_up_sync(0xffffffffu, inc, o);
        if (lane >= o) inc += t;
    }
    if (lane == 31) ws[w] = inc;
    __syncthreads();
    int off = 0;
    for (int k = 0; k < w; k++) off += ws[k];
    int excl = off + inc - v;
    if (tid < NB) g_boff[tid] = excl;
    if (tid == NB - 1) g_rowptr[N_NODES] = excl + v;
}

// Pass C: per-chunk local exclusive scan + global offset -> rowptr/fill.
__global__ void k_scanc() {
    __shared__ int wsum[32];
    int tid = threadIdx.x, lane = tid & 31, w = tid >> 5;
    int i = blockIdx.x * 1024 + tid;
    int v = (i < N_NODES) ? g_cnt[i] : 0;
    int inc = v;
#pragma unroll
    for (int o = 1; o < 32; o <<= 1) {
        int t = __shfl_up_sync(0xffffffffu, inc, o);
        if (lane >= o) inc += t;
    }
    if (lane == 31) wsum[w] = inc;
    __syncthreads();
    if (w == 0) {
        int s = wsum[lane];
        int si = s;
#pragma unroll
        for (int o = 1; o < 32; o <<= 1) {
            int t = __shfl_up_sync(0xffffffffu, si, o);
            if (lane >= o) si += t;
        }
        wsum[lane] = si - s;
    }
    __syncthreads();
    if (i < N_NODES) {
        int excl = g_boff[blockIdx.x] + wsum[w] + inc - v;
        g_rowptr[i] = excl;
        g_fill[i]   = excl;
    }
}

__global__ void k_bin(const int* __restrict__ ei) {
    int e = blockIdx.x * blockDim.x + threadIdx.x;
    if (e >= N_EDGES) return;
    int s = ei[e];
    int d = ei[N_EDGES + e];
    float cf = g_dinv[s] * g_dinv[d];
    int pos = atomicAdd(&g_fill[d], 1);
    g_edge[pos] = make_int2(s, __float_as_int(cf));
}

// ---------------- tf32 MMA GEMM (3xtf32 split for fp32 accuracy) ----------------
__device__ __forceinline__ uint32_t f2tf(float v) {
    uint32_t r;
    asm("cvt.rna.tf32.f32 %0, %1;" : "=r"(r) : "f"(v));
    return r;
}
__device__ __forceinline__ void split_tf(float v, uint32_t& hi, uint32_t& lo) {
    hi = f2tf(v);
    lo = f2tf(v - __uint_as_float(hi));
}
__device__ __forceinline__ void mma8(float4& d, const uint32_t* a, uint32_t b0, uint32_t b1) {
    asm volatile(
        "mma.sync.aligned.m16n8k8.row.col.f32.tf32.tf32.f32 "
        "{%0,%1,%2,%3}, {%4,%5,%6,%7}, {%8,%9}, {%0,%1,%2,%3};"
        : "+f"(d.x), "+f"(d.y), "+f"(d.z), "+f"(d.w)
        : "r"(a[0]), "r"(a[1]), "r"(a[2]), "r"(a[3]), "r"(b0), "r"(b1));
}

// H = X @ W (100000x64 @ 64x64). 128 threads = 4 warps; 16 rows/warp = 64 rows/block.
// Writes fp32 g_h (self term) and half2 g_hh (gather copy).
template <int SRC>  // 0: X = input x, 1: X = g_t
__global__ void __launch_bounds__(128) k_gemm(const float* __restrict__ Xin,
                                              const float* __restrict__ W) {
    __shared__ __align__(16) float sX[64 * 68];
    __shared__ __align__(16) float sW[64 * 72];
    const float* X = (SRC == 0) ? Xin : (const float*)g_t;
    int tid = threadIdx.x, warp = tid >> 5, lane = tid & 31;
    int g = lane >> 2, tq = lane & 3;
    int rowbase = blockIdx.x * 64;

    for (int i = tid; i < 1024; i += 128) {
        int k = i >> 4, c4 = (i & 15) << 2;
        float4 w = reinterpret_cast<const float4*>(W)[i];
        *reinterpret_cast<float4*>(&sW[k * 72 + c4]) = w;
    }
    for (int i = tid; i < 1024; i += 128) {
        int r = i >> 4, c4i = i & 15;
        int gr = rowbase + r;
        float4 v = (gr < N_NODES)
                       ? reinterpret_cast<const float4*>(X + (size_t)gr * D)[c4i]
                       : make_float4(0.f, 0.f, 0.f, 0.f);
        *reinterpret_cast<float4*>(&sX[r * 68 + (c4i << 2)]) = v;
    }
    __syncthreads();

    int wr = warp * 16;
    float4 acc[8];
#pragma unroll
    for (int nt = 0; nt < 8; nt++) acc[nt] = make_float4(0.f, 0.f, 0.f, 0.f);

#pragma unroll
    for (int kt = 0; kt < 8; kt++) {
        uint32_t ah[4], al[4];
        {
            float a0 = sX[(wr + g) * 68 + kt * 8 + tq];
            float a1 = sX[(wr + g + 8) * 68 + kt * 8 + tq];
            float a2 = sX[(wr + g) * 68 + kt * 8 + tq + 4];
            float a3 = sX[(wr + g + 8) * 68 + kt * 8 + tq + 4];
            split_tf(a0, ah[0], al[0]);
            split_tf(a1, ah[1], al[1]);
            split_tf(a2, ah[2], al[2]);
            split_tf(a3, ah[3], al[3]);
        }
#pragma unroll
        for (int nt = 0; nt < 8; nt++) {
            float b0f = sW[(kt * 8 + tq) * 72 + nt * 8 + g];
            float b1f = sW[(kt * 8 + tq + 4) * 72 + nt * 8 + g];
            uint32_t bh0, bl0, bh1, bl1;
            split_tf(b0f, bh0, bl0);
            split_tf(b1f, bh1, bl1);
            mma8(acc[nt], ah, bh0, bh1);
            mma8(acc[nt], al, bh0, bh1);
            mma8(acc[nt], ah, bl0, bl1);
        }
    }

    int r0 = rowbase + wr + g;
    int r1 = r0 + 8;
#pragma unroll
    for (int nt = 0; nt < 8; nt++) {
        int c = nt * 8 + tq * 2;
        if (r0 < N_NODES) {
            *reinterpret_cast<float2*>(g_h + (size_t)r0 * D + c) = make_float2(acc[nt].x, acc[nt].y);
            half2 hx = __floats2half2_rn(acc[nt].x, acc[nt].y);
            g_hh[r0 * 32 + (c >> 1)] = *reinterpret_cast<uint32_t*>(&hx);
        }
        if (r1 < N_NODES) {
            *reinterpret_cast<float2*>(g_h + (size_t)r1 * D + c) = make_float2(acc[nt].z, acc[nt].w);
            half2 hx = __floats2half2_rn(acc[nt].z, acc[nt].w);
            g_hh[r1 * 32 + (c >> 1)] = *reinterpret_cast<uint32_t*>(&hx);
        }
    }
}

// ---------------- SpMM: one warp per dst row, fp16 gathers, fp32 accumulate ----------------
// MODE 1: relu -> g_t. MODE 2: final -> out[row] and out[N_NODES + row] (dup copy).
template <int MODE>
__global__ void k_spmm(const float* __restrict__ bias, float* __restrict__ out) {
    int warp = (blockIdx.x * blockDim.x + threadIdx.x) >> 5;
    int lane = threadIdx.x & 31;
    if (warp >= N_NODES) return;
    int row = warp;
    float di = g_dinv[row];
    float sc = di * di;
    float2 hv = reinterpret_cast<const float2*>(g_h + (size_t)row * D)[lane];
    float ax = hv.x * sc, ay = hv.y * sc;
    int e = g_rowptr[row], end = g_rowptr[row + 1];
    for (; e + 8 <= end; e += 8) {
        int2 p[8];
        uint32_t v[8];
#pragma unroll
        for (int j = 0; j < 8; j++) p[j] = g_edge[e + j];
#pragma unroll
        for (int j = 0; j < 8; j++) v[j] = g_hh[p[j].x * 32 + lane];
#pragma unroll
        for (int j = 0; j < 8; j++) {
            float2 f = __half22float2(*reinterpret_cast<half2*>(&v[j]));
            float c = __int_as_float(p[j].y);
            ax += f.x * c;
            ay += f.y * c;
        }
    }
    for (; e < end; e++) {
        int2 p = g_edge[e];
        uint32_t vv = g_hh[p.x * 32 + lane];
        float2 f = __half22float2(*reinterpret_cast<half2*>(&vv));
        float c = __int_as_float(p.y);
        ax += f.x * c;
        ay += f.y * c;
    }
    float2 bv = reinterpret_cast<const float2*>(bias)[lane];
    ax += bv.x;
    ay += bv.y;
    if (MODE == 1) {
        float2 r = make_float2(fmaxf(ax, 0.f), fmaxf(ay, 0.f));
        reinterpret_cast<float2*>(g_t + (size_t)row * D)[lane] = r;
    } else {
        float2 r = make_float2(ax, ay);
        reinterpret_cast<float2*>(out + (size_t)row * D)[lane] = r;
        reinterpret_cast<float2*>(out + (size_t)(N_NODES + row) * D)[lane] = r;
    }
}

extern "C" void kernel_launch(void* const* d_in, const int* in_sizes, int n_in,
                              void* d_out, int out_size) {
    const float* x  = (const float*)d_in[0];
    const int*   ei = (const int*)d_in[1];
    const float* W1 = (const float*)d_in[2];
    const float* b1 = (const float*)d_in[3];
    const float* W2 = (const float*)d_in[4];
    const float* b2 = (const float*)d_in[5];
    float* out = (float*)d_out;

    k_zero<<<(N_NODES / 4 + 255) / 256, 256>>>();
    k_hist<<<(N_EDGES + 255) / 256, 256>>>(ei);
    k_reduce<<<NB, 1024>>>();
    k_scanb<<<1, 128>>>();
    k_scanc<<<NB, 1024>>>();
    k_bin<<<(N_EDGES + 255) / 256, 256>>>(ei);

    k_gemm<0><<<(N_NODES + 63) / 64, 128>>>(x, W1);             // g_h = x @ W1
    k_spmm<1><<<(N_NODES * 32 + 255) / 256, 256>>>(b1, out);    // g_t = relu(gcn1)
    k_gemm<1><<<(N_NODES + 63) / 64, 128>>>(x, W2);             // g_h = g_t @ W2
    k_spmm<2><<<(N_NODES * 32 + 255) / 256, 256>>>(b2, out);    // out = [h; h]
}

// round 6
// speedup vs baseline: 1.9447x; 1.0135x over previous
#include <cuda_runtime.h>
#include <cuda_fp16.h>
#include <cstdint>

#define N_NODES 100000
#define N_USERS 60000
#define N_EDGES 1200000
#define D 64
#define NB 98   // ceil(100000/1024) scan blocks

// Scratch (static device globals — no allocation allowed in kernel_launch)
__device__ int   g_cnt[N_NODES];
__device__ int   g_rowptr[N_NODES + 1];
__device__ int   g_fill[N_NODES];
__device__ float g_dinv[N_NODES];
__device__ int   g_bsum[NB];
__device__ __align__(16) int2     g_edge[N_EDGES];     // (col, coef-bits)
__device__ __align__(16) float    g_h[N_NODES * D];    // self-term: h*dinv^2 + bias (fp32)
__device__ __align__(16) uint32_t g_hh[N_NODES * 32];  // unscaled h, half2 (gather copy)
__device__ __align__(16) float    g_t[N_NODES * D];    // layer-1 activated output

// edge_index is int32 (JAX x64-disabled downcasts the int64 request).
__global__ void k_hist(const int* __restrict__ ei) {
    int e = blockIdx.x * blockDim.x + threadIdx.x;
    if (e < N_EDGES) atomicAdd(&g_cnt[ei[N_EDGES + e]], 1);
}

// Pass A: per-1024-chunk sums.
__global__ void k_reduce() {
    __shared__ int wsum[32];
    int tid = threadIdx.x, lane = tid & 31, w = tid >> 5;
    int i = blockIdx.x * 1024 + tid;
    int v = (i < N_NODES) ? g_cnt[i] : 0;
    int s = v;
#pragma unroll
    for (int o = 16; o > 0; o >>= 1) s += __shfl_down_sync(0xffffffffu, s, o);
    if (lane == 0) wsum[w] = s;
    __syncthreads();
    if (w == 0) {
        int t = wsum[lane];
#pragma unroll
        for (int o = 16; o > 0; o >>= 1) t += __shfl_down_sync(0xffffffffu, t, o);
        if (lane == 0) g_bsum[blockIdx.x] = t;
    }
}

// Pass B (fused): every block redundantly computes its global offset from the 98
// block sums (warp 0), then local exclusive scan of its chunk -> rowptr/fill/dinv.
__global__ void k_scanf() {
    __shared__ int wsum[32];
    __shared__ int s_boff;
    int tid = threadIdx.x, lane = tid & 31, w = tid >> 5;
    if (w == 0) {
        int s = 0;
        for (int j = lane; j < blockIdx.x; j += 32) s += g_bsum[j];
#pragma unroll
        for (int o = 16; o > 0; o >>= 1) s += __shfl_down_sync(0xffffffffu, s, o);
        if (lane == 0) s_boff = s;
    }
    __syncthreads();
    int i = blockIdx.x * 1024 + tid;
    int v = (i < N_NODES) ? g_cnt[i] : 0;
    if (i < N_NODES) g_dinv[i] = rsqrtf((float)v + 1.0f);
    int inc = v;
#pragma unroll
    for (int o = 1; o < 32; o <<= 1) {
        int t = __shfl_up_sync(0xffffffffu, inc, o);
        if (lane >= o) inc += t;
    }
    if (lane == 31) wsum[w] = inc;
    __syncthreads();
    if (w == 0) {
        int s = wsum[lane];
        int si = s;
#pragma unroll
        for (int o = 1; o < 32; o <<= 1) {
            int t = __shfl_up_sync(0xffffffffu, si, o);
            if (lane >= o) si += t;
        }
        wsum[lane] = si - s;
    }
    __syncthreads();
    int warpoff = wsum[w];
    if (i < N_NODES) {
        int excl = s_boff + warpoff + inc - v;
        g_rowptr[i] = excl;
        g_fill[i]   = excl;
    }
    if (blockIdx.x == NB - 1 && tid == 1023) {
        // inclusive total of the (partial) last chunk + its offset = total edges
        g_rowptr[N_NODES] = s_boff + warpoff + inc;
    }
}

__global__ void k_bin(const int* __restrict__ ei) {
    int e = blockIdx.x * blockDim.x + threadIdx.x;
    if (e >= N_EDGES) return;
    int s = ei[e];
    int d = ei[N_EDGES + e];
    float cf = g_dinv[s] * g_dinv[d];
    int pos = atomicAdd(&g_fill[d], 1);
    g_edge[pos] = make_int2(s, __float_as_int(cf));
}

// ---------------- tf32 MMA GEMM (3xtf32 split for fp32 accuracy) ----------------
__device__ __forceinline__ uint32_t f2tf(float v) {
    uint32_t r;
    asm("cvt.rna.tf32.f32 %0, %1;" : "=r"(r) : "f"(v));
    return r;
}
__device__ __forceinline__ void split_tf(float v, uint32_t& hi, uint32_t& lo) {
    hi = f2tf(v);
    lo = f2tf(v - __uint_as_float(hi));
}
__device__ __forceinline__ void mma8(float4& d, const uint32_t* a, uint32_t b0, uint32_t b1) {
    asm volatile(
        "mma.sync.aligned.m16n8k8.row.col.f32.tf32.tf32.f32 "
        "{%0,%1,%2,%3}, {%4,%5,%6,%7}, {%8,%9}, {%0,%1,%2,%3};"
        : "+f"(d.x), "+f"(d.y), "+f"(d.z), "+f"(d.w)
        : "r"(a[0]), "r"(a[1]), "r"(a[2]), "r"(a[3]), "r"(b0), "r"(b1));
}

// H = X @ W (100000x64 @ 64x64). 128 threads = 4 warps; 16 rows/warp.
// Epilogue: g_hh = half2(h) [unscaled, for gathers];
//           g_h  = h*dinv[row]^2 + bias [finished self-term].
template <int SRC>  // 0: X = input x, 1: X = g_t
__global__ void __launch_bounds__(128) k_gemm(const float* __restrict__ Xin,
                                              const float* __restrict__ W,
                                              const float* __restrict__ bias) {
    __shared__ __align__(16) float sX[64 * 68];
    __shared__ __align__(16) float sW[64 * 72];
    const float* X = (SRC == 0) ? Xin : (const float*)g_t;
    int tid = threadIdx.x, warp = tid >> 5, lane = tid & 31;
    int g = lane >> 2, tq = lane & 3;
    int rowbase = blockIdx.x * 64;

    for (int i = tid; i < 1024; i += 128) {
        int k = i >> 4, c4 = (i & 15) << 2;
        float4 w = reinterpret_cast<const float4*>(W)[i];
        *reinterpret_cast<float4*>(&sW[k * 72 + c4]) = w;
    }
    for (int i = tid; i < 1024; i += 128) {
        int r = i >> 4, c4i = i & 15;
        int gr = rowbase + r;
        float4 v = (gr < N_NODES)
                       ? reinterpret_cast<const float4*>(X + (size_t)gr * D)[c4i]
                       : make_float4(0.f, 0.f, 0.f, 0.f);
        *reinterpret_cast<float4*>(&sX[r * 68 + (c4i << 2)]) = v;
    }
    __syncthreads();

    int wr = warp * 16;
    float4 acc[8];
#pragma unroll
    for (int nt = 0; nt < 8; nt++) acc[nt] = make_float4(0.f, 0.f, 0.f, 0.f);

#pragma unroll
    for (int kt = 0; kt < 8; kt++) {
        uint32_t ah[4], al[4];
        {
            float a0 = sX[(wr + g) * 68 + kt * 8 + tq];
            float a1 = sX[(wr + g + 8) * 68 + kt * 8 + tq];
            float a2 = sX[(wr + g) * 68 + kt * 8 + tq + 4];
            float a3 = sX[(wr + g + 8) * 68 + kt * 8 + tq + 4];
            split_tf(a0, ah[0], al[0]);
            split_tf(a1, ah[1], al[1]);
            split_tf(a2, ah[2], al[2]);
            split_tf(a3, ah[3], al[3]);
        }
#pragma unroll
        for (int nt = 0; nt < 8; nt++) {
            float b0f = sW[(kt * 8 + tq) * 72 + nt * 8 + g];
            float b1f = sW[(kt * 8 + tq + 4) * 72 + nt * 8 + g];
            uint32_t bh0, bl0, bh1, bl1;
            split_tf(b0f, bh0, bl0);
            split_tf(b1f, bh1, bl1);
            mma8(acc[nt], ah, bh0, bh1);
            mma8(acc[nt], al, bh0, bh1);
            mma8(acc[nt], ah, bl0, bl1);
        }
    }

    int r0 = rowbase + wr + g;
    int r1 = r0 + 8;
    float d0 = (r0 < N_NODES) ? g_dinv[r0] : 0.f;
    float d1 = (r1 < N_NODES) ? g_dinv[r1] : 0.f;
    float sc0 = d0 * d0, sc1 = d1 * d1;
#pragma unroll
    for (int nt = 0; nt < 8; nt++) {
        int c = nt * 8 + tq * 2;
        float bx = __ldg(bias + c), by = __ldg(bias + c + 1);
        if (r0 < N_NODES) {
            half2 hx = __floats2half2_rn(acc[nt].x, acc[nt].y);
            g_hh[r0 * 32 + (c >> 1)] = *reinterpret_cast<uint32_t*>(&hx);
            *reinterpret_cast<float2*>(g_h + (size_t)r0 * D + c) =
                make_float2(acc[nt].x * sc0 + bx, acc[nt].y * sc0 + by);
        }
        if (r1 < N_NODES) {
            half2 hx = __floats2half2_rn(acc[nt].z, acc[nt].w);
            g_hh[r1 * 32 + (c >> 1)] = *reinterpret_cast<uint32_t*>(&hx);
            *reinterpret_cast<float2*>(g_h + (size_t)r1 * D + c) =
                make_float2(acc[nt].z * sc1 + bx, acc[nt].w * sc1 + by);
        }
    }
}

// ---------------- SpMM: one warp per dst row, fp16 gathers, fp32 accumulate ----------------
// Self-term+bias already folded into g_h. MODE 1: relu -> g_t. MODE 2: out + dup copy.
template <int MODE>
__global__ void k_spmm(float* __restrict__ out) {
    int warp = (blockIdx.x * blockDim.x + threadIdx.x) >> 5;
    int lane = threadIdx.x & 31;
    if (warp >= N_NODES) return;
    int row = warp;
    float2 hv = reinterpret_cast<const float2*>(g_h + (size_t)row * D)[lane];
    float ax = hv.x, ay = hv.y;
    int e = g_rowptr[row], end = g_rowptr[row + 1];
    for (; e + 8 <= end; e += 8) {
        int2 p[8];
        uint32_t v[8];
#pragma unroll
        for (int j = 0; j < 8; j++) p[j] = g_edge[e + j];
#pragma unroll
        for (int j = 0; j < 8; j++) v[j] = g_hh[p[j].x * 32 + lane];
#pragma unroll
        for (int j = 0; j < 8; j++) {
            float2 f = __half22float2(*reinterpret_cast<half2*>(&v[j]));
            float c = __int_as_float(p[j].y);
            ax += f.x * c;
            ay += f.y * c;
        }
    }
    for (; e < end; e++) {
        int2 p = g_edge[e];
        uint32_t vv = g_hh[p.x * 32 + lane];
        float2 f = __half22float2(*reinterpret_cast<half2*>(&vv));
        float c = __int_as_float(p.y);
        ax += f.x * c;
        ay += f.y * c;
    }
    if (MODE == 1) {
        float2 r = make_float2(fmaxf(ax, 0.f), fmaxf(ay, 0.f));
        reinterpret_cast<float2*>(g_t + (size_t)row * D)[lane] = r;
    } else {
        float2 r = make_float2(ax, ay);
        reinterpret_cast<float2*>(out + (size_t)row * D)[lane] = r;
        reinterpret_cast<float2*>(out + (size_t)(N_NODES + row) * D)[lane] = r;
    }
}

extern "C" void kernel_launch(void* const* d_in, const int* in_sizes, int n_in,
                              void* d_out, int out_size) {
    const float* x  = (const float*)d_in[0];
    const int*   ei = (const int*)d_in[1];
    const float* W1 = (const float*)d_in[2];
    const float* b1 = (const float*)d_in[3];
    const float* W2 = (const float*)d_in[4];
    const float* b2 = (const float*)d_in[5];
    float* out = (float*)d_out;

    void* cnt_ptr = nullptr;
    cudaGetSymbolAddress(&cnt_ptr, g_cnt);
    cudaMemsetAsync(cnt_ptr, 0, N_NODES * sizeof(int));

    k_hist<<<(N_EDGES + 255) / 256, 256>>>(ei);
    k_reduce<<<NB, 1024>>>();
    k_scanf<<<NB, 1024>>>();
    k_bin<<<(N_EDGES + 255) / 256, 256>>>(ei);

    k_gemm<0><<<(N_NODES + 63) / 64, 128>>>(x, W1, b1);         // g_h/g_hh = x @ W1
    k_spmm<1><<<(N_NODES * 32 + 255) / 256, 256>>>(out);        // g_t = relu(gcn1)
    k_gemm<1><<<(N_NODES + 63) / 64, 128>>>(x, W2, b2);         // g_h/g_hh = g_t @ W2
    k_spmm<2><<<(N_NODES * 32 + 255) / 256, 256>>>(out);        // out = [h; h]
}

// round 7
// speedup vs baseline: 2.0590x; 1.0588x over previous
#include <cuda_runtime.h>
#include <cuda_fp16.h>
#include <cstdint>

#define N_NODES 100000
#define N_USERS 60000
#define N_EDGES 1200000
#define D 64
#define NB 98   // ceil(100000/1024) scan blocks

// Scratch (static device globals — no allocation allowed in kernel_launch)
__device__ int   g_cnt[N_NODES];
__device__ int   g_rowptr[N_NODES + 1];
__device__ int   g_fill[N_NODES];
__device__ float g_dinv[N_NODES];
__device__ int   g_bsum[NB];
__device__ __align__(16) int2     g_edge[N_EDGES];     // (col, coef-bits)
__device__ __align__(16) float    g_h[N_NODES * D];    // X @ W, fp32 (self term)
__device__ __align__(16) uint32_t g_hh[N_NODES * 32];  // X @ W, half2 (gather copy)
__device__ __align__(16) float    g_t[N_NODES * D];    // layer-1 activated output

// edge_index is int32 (JAX x64-disabled downcasts the int64 request).
__global__ void k_hist(const int* __restrict__ ei) {
    int e = blockIdx.x * blockDim.x + threadIdx.x;
    if (e < N_EDGES) atomicAdd(&g_cnt[ei[N_EDGES + e]], 1);
}

// Pass A: per-1024-chunk sums.
__global__ void k_reduce() {
    __shared__ int wsum[32];
    int tid = threadIdx.x, lane = tid & 31, w = tid >> 5;
    int i = blockIdx.x * 1024 + tid;
    int v = (i < N_NODES) ? g_cnt[i] : 0;
    int s = v;
#pragma unroll
    for (int o = 16; o > 0; o >>= 1) s += __shfl_down_sync(0xffffffffu, s, o);
    if (lane == 0) wsum[w] = s;
    __syncthreads();
    if (w == 0) {
        int t = wsum[lane];
#pragma unroll
        for (int o = 16; o > 0; o >>= 1) t += __shfl_down_sync(0xffffffffu, t, o);
        if (lane == 0) g_bsum[blockIdx.x] = t;
    }
}

// Pass B (fused): every block redundantly computes its global offset from the 98
// block sums (warp 0), then local exclusive scan of its chunk -> rowptr/fill/dinv.
__global__ void k_scanf() {
    __shared__ int wsum[32];
    __shared__ int s_boff;
    int tid = threadIdx.x, lane = tid & 31, w = tid >> 5;
    if (w == 0) {
        int s = 0;
        for (int j = lane; j < blockIdx.x; j += 32) s += g_bsum[j];
#pragma unroll
        for (int o = 16; o > 0; o >>= 1) s += __shfl_down_sync(0xffffffffu, s, o);
        if (lane == 0) s_boff = s;
    }
    __syncthreads();
    int i = blockIdx.x * 1024 + tid;
    int v = (i < N_NODES) ? g_cnt[i] : 0;
    if (i < N_NODES) g_dinv[i] = rsqrtf((float)v + 1.0f);
    int inc = v;
#pragma unroll
    for (int o = 1; o < 32; o <<= 1) {
        int t = __shfl_up_sync(0xffffffffu, inc, o);
        if (lane >= o) inc += t;
    }
    if (lane == 31) wsum[w] = inc;
    __syncthreads();
    if (w == 0) {
        int s = wsum[lane];
        int si = s;
#pragma unroll
        for (int o = 1; o < 32; o <<= 1) {
            int t = __shfl_up_sync(0xffffffffu, si, o);
            if (lane >= o) si += t;
        }
        wsum[lane] = si - s;
    }
    __syncthreads();
    int warpoff = wsum[w];
    if (i < N_NODES) {
        int excl = s_boff + warpoff + inc - v;
        g_rowptr[i] = excl;
        g_fill[i]   = excl;
    }
    if (blockIdx.x == NB - 1 && tid == 1023) {
        g_rowptr[N_NODES] = s_boff + warpoff + inc;
    }
}

__global__ void k_bin(const int* __restrict__ ei) {
    int e = blockIdx.x * blockDim.x + threadIdx.x;
    if (e >= N_EDGES) return;
    int s = ei[e];
    int d = ei[N_EDGES + e];
    float cf = g_dinv[s] * g_dinv[d];
    int pos = atomicAdd(&g_fill[d], 1);
    g_edge[pos] = make_int2(s, __float_as_int(cf));
}

// ---------------- tf32 MMA GEMM (3xtf32 split for fp32 accuracy) ----------------
__device__ __forceinline__ uint32_t f2tf(float v) {
    uint32_t r;
    asm("cvt.rna.tf32.f32 %0, %1;" : "=r"(r) : "f"(v));
    return r;
}
__device__ __forceinline__ void split_tf(float v, uint32_t& hi, uint32_t& lo) {
    hi = f2tf(v);
    lo = f2tf(v - __uint_as_float(hi));
}
__device__ __forceinline__ void mma8(float4& d, const uint32_t* a, uint32_t b0, uint32_t b1) {
    asm volatile(
        "mma.sync.aligned.m16n8k8.row.col.f32.tf32.tf32.f32 "
        "{%0,%1,%2,%3}, {%4,%5,%6,%7}, {%8,%9}, {%0,%1,%2,%3};"
        : "+f"(d.x), "+f"(d.y), "+f"(d.z), "+f"(d.w)
        : "r"(a[0]), "r"(a[1]), "r"(a[2]), "r"(a[3]), "r"(b0), "r"(b1));
}

// H = X @ W (100000x64 @ 64x64). 128 threads = 4 warps; 16 rows/warp.
// Writes fp32 g_h and half2 g_hh (both unscaled). No CSR dependency.
template <int SRC>  // 0: X = input x, 1: X = g_t
__global__ void __launch_bounds__(128) k_gemm(const float* __restrict__ Xin,
                                              const float* __restrict__ W) {
    __shared__ __align__(16) float sX[64 * 68];
    __shared__ __align__(16) float sW[64 * 72];
    const float* X = (SRC == 0) ? Xin : (const float*)g_t;
    int tid = threadIdx.x, warp = tid >> 5, lane = tid & 31;
    int g = lane >> 2, tq = lane & 3;
    int rowbase = blockIdx.x * 64;

    for (int i = tid; i < 1024; i += 128) {
        int k = i >> 4, c4 = (i & 15) << 2;
        float4 w = reinterpret_cast<const float4*>(W)[i];
        *reinterpret_cast<float4*>(&sW[k * 72 + c4]) = w;
    }
    for (int i = tid; i < 1024; i += 128) {
        int r = i >> 4, c4i = i & 15;
        int gr = rowbase + r;
        float4 v = (gr < N_NODES)
                       ? reinterpret_cast<const float4*>(X + (size_t)gr * D)[c4i]
                       : make_float4(0.f, 0.f, 0.f, 0.f);
        *reinterpret_cast<float4*>(&sX[r * 68 + (c4i << 2)]) = v;
    }
    __syncthreads();

    int wr = warp * 16;
    float4 acc[8];
#pragma unroll
    for (int nt = 0; nt < 8; nt++) acc[nt] = make_float4(0.f, 0.f, 0.f, 0.f);

#pragma unroll
    for (int kt = 0; kt < 8; kt++) {
        uint32_t ah[4], al[4];
        {
            float a0 = sX[(wr + g) * 68 + kt * 8 + tq];
            float a1 = sX[(wr + g + 8) * 68 + kt * 8 + tq];
            float a2 = sX[(wr + g) * 68 + kt * 8 + tq + 4];
            float a3 = sX[(wr + g + 8) * 68 + kt * 8 + tq + 4];
            split_tf(a0, ah[0], al[0]);
            split_tf(a1, ah[1], al[1]);
            split_tf(a2, ah[2], al[2]);
            split_tf(a3, ah[3], al[3]);
        }
#pragma unroll
        for (int nt = 0; nt < 8; nt++) {
            float b0f = sW[(kt * 8 + tq) * 72 + nt * 8 + g];
            float b1f = sW[(kt * 8 + tq + 4) * 72 + nt * 8 + g];
            uint32_t bh0, bl0, bh1, bl1;
            split_tf(b0f, bh0, bl0);
            split_tf(b1f, bh1, bl1);
            mma8(acc[nt], ah, bh0, bh1);
            mma8(acc[nt], al, bh0, bh1);
            mma8(acc[nt], ah, bl0, bl1);
        }
    }

    int r0 = rowbase + wr + g;
    int r1 = r0 + 8;
#pragma unroll
    for (int nt = 0; nt < 8; nt++) {
        int c = nt * 8 + tq * 2;
        if (r0 < N_NODES) {
            *reinterpret_cast<float2*>(g_h + (size_t)r0 * D + c) = make_float2(acc[nt].x, acc[nt].y);
            half2 hx = __floats2half2_rn(acc[nt].x, acc[nt].y);
            g_hh[r0 * 32 + (c >> 1)] = *reinterpret_cast<uint32_t*>(&hx);
        }
        if (r1 < N_NODES) {
            *reinterpret_cast<float2*>(g_h + (size_t)r1 * D + c) = make_float2(acc[nt].z, acc[nt].w);
            half2 hx = __floats2half2_rn(acc[nt].z, acc[nt].w);
            g_hh[r1 * 32 + (c >> 1)] = *reinterpret_cast<uint32_t*>(&hx);
        }
    }
}

// ---------------- SpMM: one warp per dst row, fp16 gathers, fp32 accumulate ----------------
// MODE 1: relu -> g_t. MODE 2: final -> out[row] and out[N_NODES + row] (dup copy).
template <int MODE>
__global__ void __launch_bounds__(128) k_spmm(const float* __restrict__ bias,
                                              float* __restrict__ out) {
    int warp = (blockIdx.x * blockDim.x + threadIdx.x) >> 5;
    int lane = threadIdx.x & 31;
    if (warp >= N_NODES) return;
    int row = warp;
    float di = g_dinv[row];
    float sc = di * di;
    float2 hv = reinterpret_cast<const float2*>(g_h + (size_t)row * D)[lane];
    float ax = hv.x * sc, ay = hv.y * sc;
    int e = g_rowptr[row], end = g_rowptr[row + 1];
    for (; e + 8 <= end; e += 8) {
        int2 p[8];
        uint32_t v[8];
#pragma unroll
        for (int j = 0; j < 8; j++) p[j] = g_edge[e + j];
#pragma unroll
        for (int j = 0; j < 8; j++) v[j] = g_hh[p[j].x * 32 + lane];
#pragma unroll
        for (int j = 0; j < 8; j++) {
            float2 f = __half22float2(*reinterpret_cast<half2*>(&v[j]));
            float c = __int_as_float(p[j].y);
            ax += f.x * c;
            ay += f.y * c;
        }
    }
    for (; e < end; e++) {
        int2 p = g_edge[e];
        uint32_t vv = g_hh[p.x * 32 + lane];
        float2 f = __half22float2(*reinterpret_cast<half2*>(&vv));
        float c = __int_as_float(p.y);
        ax += f.x * c;
        ay += f.y * c;
    }
    float2 bv = reinterpret_cast<const float2*>(bias)[lane];
    ax += bv.x;
    ay += bv.y;
    if (MODE == 1) {
        float2 r = make_float2(fmaxf(ax, 0.f), fmaxf(ay, 0.f));
        reinterpret_cast<float2*>(g_t + (size_t)row * D)[lane] = r;
    } else {
        float2 r = make_float2(ax, ay);
        reinterpret_cast<float2*>(out + (size_t)row * D)[lane] = r;
        reinterpret_cast<float2*>(out + (size_t)(N_NODES + row) * D)[lane] = r;
    }
}

extern "C" void kernel_launch(void* const* d_in, const int* in_sizes, int n_in,
                              void* d_out, int out_size) {
    const float* x  = (const float*)d_in[0];
    const int*   ei = (const int*)d_in[1];
    const float* W1 = (const float*)d_in[2];
    const float* b1 = (const float*)d_in[3];
    const float* W2 = (const float*)d_in[4];
    const float* b2 = (const float*)d_in[5];
    float* out = (float*)d_out;

    // One-time infra (created on the uncaptured correctness call; no device
    // memory is allocated by stream/event creation).
    static cudaStream_t s1 = nullptr;
    static cudaEvent_t ev_fork = nullptr, ev_join = nullptr;
    if (s1 == nullptr) {
        cudaStreamCreateWithFlags(&s1, cudaStreamNonBlocking);
        cudaEventCreateWithFlags(&ev_fork, cudaEventDisableTiming);
        cudaEventCreateWithFlags(&ev_join, cudaEventDisableTiming);
    }

    void* cnt_ptr = nullptr;
    cudaGetSymbolAddress(&cnt_ptr, g_cnt);

    // Fork: gemm0 runs on s1 concurrently with the CSR build on the main stream.
    cudaEventRecord(ev_fork, 0);
    cudaStreamWaitEvent(s1, ev_fork, 0);
    k_gemm<0><<<(N_NODES + 63) / 64, 128, 0, s1>>>(x, W1);      // g_h/g_hh = x @ W1
    cudaEventRecord(ev_join, s1);

    // CSR build chain on the main stream.
    cudaMemsetAsync(cnt_ptr, 0, N_NODES * sizeof(int));
    k_hist<<<(N_EDGES + 255) / 256, 256>>>(ei);
    k_reduce<<<NB, 1024>>>();
    k_scanf<<<NB, 1024>>>();
    k_bin<<<(N_EDGES + 255) / 256, 256>>>(ei);

    // Join: spmm1 needs both the CSR and gemm0's output.
    cudaStreamWaitEvent(0, ev_join, 0);
    k_spmm<1><<<(N_NODES * 32 + 127) / 128, 128>>>(b1, out);    // g_t = relu(gcn1)
    k_gemm<1><<<(N_NODES + 63) / 64, 128>>>(x, W2);             // g_h/g_hh = g_t @ W2
    k_spmm<2><<<(N_NODES * 32 + 127) / 128, 128>>>(b2, out);    // out = [h; h]
}